// round 11
// baseline (speedup 1.0000x reference)
#include <cuda_runtime.h>

// B=4, H=8, S=2048, D=3 (fixed by reference)
typedef unsigned long long u64;

#define S_LEN   2048
#define QPC     64            // queries per CTA
#define THREADS 128           // 4 key-groups x 32 lanes (1 warp = 1 group); 2 queries/thread
#define N_CTA   1024          // 32 bh * 32 chunks
#define GROUPS  4
#define QPT     2
#define RECS    256           // 2-key records per group (512 keys/group)
#define GSTRIDE 6160          // 256*24 + 16 pad (bank spread between groups)
#define OUT_HALF (32 * S_LEN * 3)
#define SMEM_BYTES (GROUPS * GSTRIDE)   // 24640 B

__device__ __forceinline__ u64 fma2(u64 a, u64 b, u64 c) {
    u64 d; asm("fma.rn.f32x2 %0, %1, %2, %3;" : "=l"(d) : "l"(a), "l"(b), "l"(c));
    return d;
}
__device__ __forceinline__ u64 mul2(u64 a, u64 b) {
    u64 d; asm("mul.rn.f32x2 %0, %1, %2;" : "=l"(d) : "l"(a), "l"(b));
    return d;
}
__device__ __forceinline__ u64 add2(u64 a, u64 b) {
    u64 d; asm("add.rn.f32x2 %0, %1, %2;" : "=l"(d) : "l"(a), "l"(b));
    return d;
}
__device__ __forceinline__ u64 ex2_2(u64 x) {
    u64 r;
    asm("{\n\t"
        ".reg .f32 lo, hi;\n\t"
        "mov.b64 {lo, hi}, %1;\n\t"
        "ex2.approx.f32 lo, lo;\n\t"
        "ex2.approx.f32 hi, hi;\n\t"
        "mov.b64 %0, {lo, hi};\n\t"
        "}" : "=l"(r) : "l"(x));
    return r;
}
__device__ __forceinline__ u64 pack2(float lo, float hi) {
    u64 r; asm("mov.b64 %0, {%1, %2};" : "=l"(r) : "f"(lo), "f"(hi));
    return r;
}
__device__ __forceinline__ void unpack2(u64 v, float& lo, float& hi) {
    asm("mov.b64 {%0, %1}, %2;" : "=f"(lo), "=f"(hi) : "l"(v));
}
__device__ __forceinline__ float rcpa(float x) {
    float r; asm("rcp.approx.f32 %0, %1;" : "=f"(r) : "f"(x));
    return r;
}
__device__ __forceinline__ u64 lds64(unsigned addr) {
    u64 v; asm("ld.shared.b64 %0, [%1];" : "=l"(v) : "r"(addr));
    return v;
}

__global__ __launch_bounds__(THREADS, 7)
void attn3d_kernel(const float* __restrict__ x,
                   const float* __restrict__ Wq,
                   const float* __restrict__ Wk,
                   const float* __restrict__ Wv,
                   float* __restrict__ out)
{
    extern __shared__ float sm[];
    float* red = sm;   // aliases x region after post-loop barrier (1024 floats)

    const int tid   = threadIdx.x;
    const int cta   = blockIdx.x;
    const int bh    = cta >> 5;
    const int chunk = cta & 31;
    const int b     = bh >> 3;
    const int h     = bh & 7;

    const float* xb = x + (size_t)b * S_LEN * 3;

    // ---- Fill smem: 2-key records [x0 pair][x1 pair][x2 pair], 24B each ----
    #pragma unroll
    for (int i = 0; i < S_LEN / THREADS; ++i) {
        const int k  = tid + i * THREADS;
        const int g  = k >> 9;             // key group (512 keys each)
        const int jc = k & 511;
        const int j  = jc >> 1;            // record in group
        const int c  = jc & 1;             // lane in record
        float* rec = reinterpret_cast<float*>(
            reinterpret_cast<char*>(sm) + g * GSTRIDE + j * 24 + c * 4);
        rec[0] = xb[k * 3 + 0];
        rec[2] = xb[k * 3 + 1];
        rec[4] = xb[k * 3 + 2];
    }

    // ---- 2 queries per thread; fold Wq*Wk*scale; no shift (range-safe) ----
    const int g  = tid >> 5;          // key group == warp id
    const int ql = tid & 31;          // query slot; handles ql and ql+32
    const float* wq = Wq + h * 9;
    const float* wk = Wk + h * 9;
    const float RS = 0.57735026918962576f * 1.4426950408889634f;

    u64 q0p[QPT], q1p[QPT], q2p[QPT];
    #pragma unroll
    for (int qq = 0; qq < QPT; ++qq) {
        const int sq = chunk * QPC + ql + qq * 32;
        const float xq0 = xb[sq * 3 + 0];
        const float xq1 = xb[sq * 3 + 1];
        const float xq2 = xb[sq * 3 + 2];
        const float q0 = xq0 * wq[0] + xq1 * wq[3] + xq2 * wq[6];
        const float q1 = xq0 * wq[1] + xq1 * wq[4] + xq2 * wq[7];
        const float q2 = xq0 * wq[2] + xq1 * wq[5] + xq2 * wq[8];
        const float a0 = RS * (q0 * wk[0] + q1 * wk[1] + q2 * wk[2]);
        const float a1 = RS * (q0 * wk[3] + q1 * wk[4] + q2 * wk[5]);
        const float a2 = RS * (q0 * wk[6] + q1 * wk[7] + q2 * wk[8]);
        q0p[qq] = pack2(a0, a0);
        q1p[qq] = pack2(a1, a1);
        q2p[qq] = pack2(a2, a2);
    }

    __syncthreads();

    unsigned sbase;
    asm("{ .reg .u64 t; cvta.to.shared.u64 t, %1; cvt.u32.u64 %0, t; }"
        : "=r"(sbase) : "l"(sm));
    unsigned p = sbase + g * GSTRIDE;

    u64 lacc[QPT] = {0ull, 0ull};
    u64 t0[QPT]   = {0ull, 0ull};
    u64 t1[QPT]   = {0ull, 0ull};
    u64 t2[QPT]   = {0ull, 0ull};

    // ---- Depth-2 software pipeline over 256 records ----
    // iter j: exp(d_j) ; load rec[j+2] ; dots(rec[j+1]) ; accum(p_j, rec[j])
    u64 A0 = lds64(p),      A1 = lds64(p + 8),  A2 = lds64(p + 16);
    u64 B0 = lds64(p + 24), B1 = lds64(p + 32), B2 = lds64(p + 40);
    p += 48;
    u64 d0 = fma2(q0p[0], A0, fma2(q1p[0], A1, mul2(q2p[0], A2)));
    u64 d1 = fma2(q0p[1], A0, fma2(q1p[1], A1, mul2(q2p[1], A2)));

    #pragma unroll 4
    for (int r = 0; r < RECS - 2; ++r) {
        const u64 e0 = ex2_2(d0);
        const u64 e1 = ex2_2(d1);
        const u64 C0 = lds64(p);
        const u64 C1 = lds64(p + 8);
        const u64 C2 = lds64(p + 16);
        p += 24;
        const u64 n0 = fma2(q0p[0], B0, fma2(q1p[0], B1, mul2(q2p[0], B2)));
        const u64 n1 = fma2(q0p[1], B0, fma2(q1p[1], B1, mul2(q2p[1], B2)));
        lacc[0] = add2(lacc[0], e0);
        t0[0]   = fma2(e0, A0, t0[0]);
        t1[0]   = fma2(e0, A1, t1[0]);
        t2[0]   = fma2(e0, A2, t2[0]);
        lacc[1] = add2(lacc[1], e1);
        t0[1]   = fma2(e1, A0, t0[1]);
        t1[1]   = fma2(e1, A1, t1[1]);
        t2[1]   = fma2(e1, A2, t2[1]);
        A0 = B0; A1 = B1; A2 = B2;
        B0 = C0; B1 = C1; B2 = C2;
        d0 = n0; d1 = n1;
    }
    // tail 1: record RECS-2 (in A), dots for RECS-1 (in B)
    {
        const u64 e0 = ex2_2(d0);
        const u64 e1 = ex2_2(d1);
        const u64 n0 = fma2(q0p[0], B0, fma2(q1p[0], B1, mul2(q2p[0], B2)));
        const u64 n1 = fma2(q0p[1], B0, fma2(q1p[1], B1, mul2(q2p[1], B2)));
        lacc[0] = add2(lacc[0], e0);
        t0[0] = fma2(e0, A0, t0[0]); t1[0] = fma2(e0, A1, t1[0]); t2[0] = fma2(e0, A2, t2[0]);
        lacc[1] = add2(lacc[1], e1);
        t0[1] = fma2(e1, A0, t0[1]); t1[1] = fma2(e1, A1, t1[1]); t2[1] = fma2(e1, A2, t2[1]);
        d0 = n0; d1 = n1;
        A0 = B0; A1 = B1; A2 = B2;
    }
    // tail 2: record RECS-1 (in A)
    {
        const u64 e0 = ex2_2(d0);
        const u64 e1 = ex2_2(d1);
        lacc[0] = add2(lacc[0], e0);
        t0[0] = fma2(e0, A0, t0[0]); t1[0] = fma2(e0, A1, t1[0]); t2[0] = fma2(e0, A2, t2[0]);
        lacc[1] = add2(lacc[1], e1);
        t0[1] = fma2(e1, A0, t0[1]); t1[1] = fma2(e1, A1, t1[1]); t2[1] = fma2(e1, A2, t2[1]);
    }

    // ---- All reads done; alias smem for reduction ----
    __syncthreads();
    #pragma unroll
    for (int qq = 0; qq < QPT; ++qq) {
        const int q = ql + qq * 32;
        float a, c;
        unpack2(lacc[qq], a, c); red[0 * 256 + g * 64 + q] = a + c;
        unpack2(t0[qq],   a, c); red[1 * 256 + g * 64 + q] = a + c;
        unpack2(t1[qq],   a, c); red[2 * 256 + g * 64 + q] = a + c;
        unpack2(t2[qq],   a, c); red[3 * 256 + g * 64 + q] = a + c;
    }
    __syncthreads();

    // ---- 4-way group merge + Wv projection + write both output copies ----
    if (tid < QPC) {
        const float L  = red[0 * 256 + tid] + red[0 * 256 + 64 + tid]
                       + red[0 * 256 + 128 + tid] + red[0 * 256 + 192 + tid];
        const float T0 = red[1 * 256 + tid] + red[1 * 256 + 64 + tid]
                       + red[1 * 256 + 128 + tid] + red[1 * 256 + 192 + tid];
        const float T1 = red[2 * 256 + tid] + red[2 * 256 + 64 + tid]
                       + red[2 * 256 + 128 + tid] + red[2 * 256 + 192 + tid];
        const float T2 = red[3 * 256 + tid] + red[3 * 256 + 64 + tid]
                       + red[3 * 256 + 128 + tid] + red[3 * 256 + 192 + tid];
        const float inv = rcpa(L);
        const float* wv = Wv + h * 9;
        const float r0 = (T0 * wv[0] + T1 * wv[3] + T2 * wv[6]) * inv;
        const float r1 = (T0 * wv[1] + T1 * wv[4] + T2 * wv[7]) * inv;
        const float r2 = (T0 * wv[2] + T1 * wv[5] + T2 * wv[8]) * inv;
        const int base = (bh * S_LEN + chunk * QPC + tid) * 3;
        out[base + 0] = r0;
        out[base + 1] = r1;
        out[base + 2] = r2;
        out[OUT_HALF + base + 0] = r0;
        out[OUT_HALF + base + 1] = r1;
        out[OUT_HALF + base + 2] = r2;
    }
}

extern "C" void kernel_launch(void* const* d_in, const int* in_sizes, int n_in,
                              void* d_out, int out_size)
{
    const float* x  = (const float*)d_in[0];
    const float* Wq = (const float*)d_in[1];
    const float* Wk = (const float*)d_in[2];
    const float* Wv = (const float*)d_in[3];
    float* out = (float*)d_out;

    cudaFuncSetAttribute(attn3d_kernel,
                         cudaFuncAttributeMaxDynamicSharedMemorySize, SMEM_BYTES);
    attn3d_kernel<<<N_CTA, THREADS, SMEM_BYTES>>>(x, Wq, Wk, Wv, out);
}

// round 12
// speedup vs baseline: 1.0452x; 1.0452x over previous
#include <cuda_runtime.h>

// B=4, H=8, S=2048, D=3 (fixed by reference)
typedef unsigned long long u64;

#define S_LEN   2048
#define QPC     64            // queries per CTA
#define THREADS 128           // 4 key-groups x 32 lanes (1 warp = 1 group); 2 queries/thread
#define N_CTA   1024          // 32 bh * 32 chunks
#define GROUPS  4
#define QPT     2
#define ITERS   128           // bodies of 2 records (4 keys); 512 keys/group
#define GSTRIDE 6160          // 256*24 + 16 pad (bank spread between groups)
#define OUT_HALF (32 * S_LEN * 3)
#define SMEM_BYTES (GROUPS * GSTRIDE)   // 24640 B

__device__ __forceinline__ u64 fma2(u64 a, u64 b, u64 c) {
    u64 d; asm("fma.rn.f32x2 %0, %1, %2, %3;" : "=l"(d) : "l"(a), "l"(b), "l"(c));
    return d;
}
__device__ __forceinline__ u64 mul2(u64 a, u64 b) {
    u64 d; asm("mul.rn.f32x2 %0, %1, %2;" : "=l"(d) : "l"(a), "l"(b));
    return d;
}
__device__ __forceinline__ u64 add2(u64 a, u64 b) {
    u64 d; asm("add.rn.f32x2 %0, %1, %2;" : "=l"(d) : "l"(a), "l"(b));
    return d;
}
__device__ __forceinline__ u64 ex2_2(u64 x) {
    u64 r;
    asm("{\n\t"
        ".reg .f32 lo, hi;\n\t"
        "mov.b64 {lo, hi}, %1;\n\t"
        "ex2.approx.f32 lo, lo;\n\t"
        "ex2.approx.f32 hi, hi;\n\t"
        "mov.b64 %0, {lo, hi};\n\t"
        "}" : "=l"(r) : "l"(x));
    return r;
}
__device__ __forceinline__ u64 pack2(float lo, float hi) {
    u64 r; asm("mov.b64 %0, {%1, %2};" : "=l"(r) : "f"(lo), "f"(hi));
    return r;
}
__device__ __forceinline__ void unpack2(u64 v, float& lo, float& hi) {
    asm("mov.b64 {%0, %1}, %2;" : "=f"(lo), "=f"(hi) : "l"(v));
}
__device__ __forceinline__ float rcpa(float x) {
    float r; asm("rcp.approx.f32 %0, %1;" : "=f"(r) : "f"(x));
    return r;
}
__device__ __forceinline__ u64 lds64(unsigned addr) {
    u64 v; asm("ld.shared.b64 %0, [%1];" : "=l"(v) : "r"(addr));
    return v;
}

__global__ __launch_bounds__(THREADS, 7)
void attn3d_kernel(const float* __restrict__ x,
                   const float* __restrict__ Wq,
                   const float* __restrict__ Wk,
                   const float* __restrict__ Wv,
                   float* __restrict__ out)
{
    extern __shared__ float sm[];
    float* red = sm;   // aliases x region after post-loop barrier (1024 floats)

    const int tid   = threadIdx.x;
    const int cta   = blockIdx.x;
    const int bh    = cta >> 5;
    const int chunk = cta & 31;
    const int b     = bh >> 3;
    const int h     = bh & 7;

    const float* xb = x + (size_t)b * S_LEN * 3;

    // ---- Fill smem: 2-key records [x0 pair][x1 pair][x2 pair], 24B each ----
    #pragma unroll
    for (int i = 0; i < S_LEN / THREADS; ++i) {
        const int k  = tid + i * THREADS;
        const int g  = k >> 9;             // key group (512 keys each)
        const int jc = k & 511;
        const int j  = jc >> 1;            // record in group
        const int c  = jc & 1;             // lane in record
        float* rec = reinterpret_cast<float*>(
            reinterpret_cast<char*>(sm) + g * GSTRIDE + j * 24 + c * 4);
        rec[0] = xb[k * 3 + 0];
        rec[2] = xb[k * 3 + 1];
        rec[4] = xb[k * 3 + 2];
    }

    // ---- 2 queries per thread; fold Wq*Wk*scale; no shift (range-safe) ----
    const int g  = tid >> 5;          // key group == warp id
    const int ql = tid & 31;          // query slot; handles ql and ql+32
    const float* wq = Wq + h * 9;
    const float* wk = Wk + h * 9;
    const float RS = 0.57735026918962576f * 1.4426950408889634f;

    u64 q0p[QPT], q1p[QPT], q2p[QPT];
    #pragma unroll
    for (int qq = 0; qq < QPT; ++qq) {
        const int sq = chunk * QPC + ql + qq * 32;
        const float xq0 = xb[sq * 3 + 0];
        const float xq1 = xb[sq * 3 + 1];
        const float xq2 = xb[sq * 3 + 2];
        const float q0 = xq0 * wq[0] + xq1 * wq[3] + xq2 * wq[6];
        const float q1 = xq0 * wq[1] + xq1 * wq[4] + xq2 * wq[7];
        const float q2 = xq0 * wq[2] + xq1 * wq[5] + xq2 * wq[8];
        const float a0 = RS * (q0 * wk[0] + q1 * wk[1] + q2 * wk[2]);
        const float a1 = RS * (q0 * wk[3] + q1 * wk[4] + q2 * wk[5]);
        const float a2 = RS * (q0 * wk[6] + q1 * wk[7] + q2 * wk[8]);
        q0p[qq] = pack2(a0, a0);
        q1p[qq] = pack2(a1, a1);
        q2p[qq] = pack2(a2, a2);
    }

    __syncthreads();

    unsigned sbase;
    asm("{ .reg .u64 t; cvta.to.shared.u64 t, %1; cvt.u32.u64 %0, t; }"
        : "=r"(sbase) : "l"(sm));
    const unsigned gbase = sbase + g * GSTRIDE;

    // CTA-dependent ring start: de-phase warps across co-resident CTAs.
    const int start = (cta * 73) & (ITERS - 1);
    unsigned p = gbase + (unsigned)start * 48u;

    u64 lacc[QPT] = {0ull, 0ull};
    u64 t0[QPT]   = {0ull, 0ull};
    u64 t1[QPT]   = {0ull, 0ull};
    u64 t2[QPT]   = {0ull, 0ull};

    // ---- Inner sweep: 2 independent records (4 keys) per body, ring order ----
    #pragma unroll 2
    for (int r = start; r < ITERS; ++r) {
        const u64 A0 = lds64(p);
        const u64 A1 = lds64(p + 8);
        const u64 A2 = lds64(p + 16);
        const u64 B0 = lds64(p + 24);
        const u64 B1 = lds64(p + 32);
        const u64 B2 = lds64(p + 40);
        p += 48;
        #pragma unroll
        for (int qq = 0; qq < QPT; ++qq) {
            const u64 dA = fma2(q0p[qq], A0, fma2(q1p[qq], A1, mul2(q2p[qq], A2)));
            const u64 dB = fma2(q0p[qq], B0, fma2(q1p[qq], B1, mul2(q2p[qq], B2)));
            const u64 pA = ex2_2(dA);
            const u64 pB = ex2_2(dB);
            lacc[qq] = add2(lacc[qq], add2(pA, pB));
            t0[qq]   = fma2(pA, A0, fma2(pB, B0, t0[qq]));
            t1[qq]   = fma2(pA, A1, fma2(pB, B1, t1[qq]));
            t2[qq]   = fma2(pA, A2, fma2(pB, B2, t2[qq]));
        }
    }
    p = gbase;
    #pragma unroll 2
    for (int r = 0; r < start; ++r) {
        const u64 A0 = lds64(p);
        const u64 A1 = lds64(p + 8);
        const u64 A2 = lds64(p + 16);
        const u64 B0 = lds64(p + 24);
        const u64 B1 = lds64(p + 32);
        const u64 B2 = lds64(p + 40);
        p += 48;
        #pragma unroll
        for (int qq = 0; qq < QPT; ++qq) {
            const u64 dA = fma2(q0p[qq], A0, fma2(q1p[qq], A1, mul2(q2p[qq], A2)));
            const u64 dB = fma2(q0p[qq], B0, fma2(q1p[qq], B1, mul2(q2p[qq], B2)));
            const u64 pA = ex2_2(dA);
            const u64 pB = ex2_2(dB);
            lacc[qq] = add2(lacc[qq], add2(pA, pB));
            t0[qq]   = fma2(pA, A0, fma2(pB, B0, t0[qq]));
            t1[qq]   = fma2(pA, A1, fma2(pB, B1, t1[qq]));
            t2[qq]   = fma2(pA, A2, fma2(pB, B2, t2[qq]));
        }
    }

    // ---- All reads done; alias smem for reduction ----
    __syncthreads();
    #pragma unroll
    for (int qq = 0; qq < QPT; ++qq) {
        const int q = ql + qq * 32;
        float a, c;
        unpack2(lacc[qq], a, c); red[0 * 256 + g * 64 + q] = a + c;
        unpack2(t0[qq],   a, c); red[1 * 256 + g * 64 + q] = a + c;
        unpack2(t1[qq],   a, c); red[2 * 256 + g * 64 + q] = a + c;
        unpack2(t2[qq],   a, c); red[3 * 256 + g * 64 + q] = a + c;
    }
    __syncthreads();

    // ---- 4-way group merge + Wv projection + write both output copies ----
    if (tid < QPC) {
        const float L  = red[0 * 256 + tid] + red[0 * 256 + 64 + tid]
                       + red[0 * 256 + 128 + tid] + red[0 * 256 + 192 + tid];
        const float T0 = red[1 * 256 + tid] + red[1 * 256 + 64 + tid]
                       + red[1 * 256 + 128 + tid] + red[1 * 256 + 192 + tid];
        const float T1 = red[2 * 256 + tid] + red[2 * 256 + 64 + tid]
                       + red[2 * 256 + 128 + tid] + red[2 * 256 + 192 + tid];
        const float T2 = red[3 * 256 + tid] + red[3 * 256 + 64 + tid]
                       + red[3 * 256 + 128 + tid] + red[3 * 256 + 192 + tid];
        const float inv = rcpa(L);
        const float* wv = Wv + h * 9;
        const float r0 = (T0 * wv[0] + T1 * wv[3] + T2 * wv[6]) * inv;
        const float r1 = (T0 * wv[1] + T1 * wv[4] + T2 * wv[7]) * inv;
        const float r2 = (T0 * wv[2] + T1 * wv[5] + T2 * wv[8]) * inv;
        const int base = (bh * S_LEN + chunk * QPC + tid) * 3;
        out[base + 0] = r0;
        out[base + 1] = r1;
        out[base + 2] = r2;
        out[OUT_HALF + base + 0] = r0;
        out[OUT_HALF + base + 1] = r1;
        out[OUT_HALF + base + 2] = r2;
    }
}

extern "C" void kernel_launch(void* const* d_in, const int* in_sizes, int n_in,
                              void* d_out, int out_size)
{
    const float* x  = (const float*)d_in[0];
    const float* Wq = (const float*)d_in[1];
    const float* Wk = (const float*)d_in[2];
    const float* Wv = (const float*)d_in[3];
    float* out = (float*)d_out;

    cudaFuncSetAttribute(attn3d_kernel,
                         cudaFuncAttributeMaxDynamicSharedMemorySize, SMEM_BYTES);
    attn3d_kernel<<<N_CTA, THREADS, SMEM_BYTES>>>(x, Wq, Wk, Wv, out);
}

// round 13
// speedup vs baseline: 1.0642x; 1.0182x over previous
#include <cuda_runtime.h>

// B=4, H=8, S=2048, D=3 (fixed by reference)
typedef unsigned long long u64;

#define S_LEN   2048
#define QPC     64            // queries per CTA
#define THREADS 128           // 4 key-groups x 32 lanes (1 warp = 1 group); 2 queries/thread
#define N_CTA   1024          // 32 bh * 32 chunks
#define GROUPS  4
#define QPT     2
#define ITERS   128           // bodies of 2 records (4 keys); 512 keys/group
#define GSTRIDE 6160          // 256*24 + 16 pad (bank spread between groups)
#define OUT_HALF (32 * S_LEN * 3)
#define SMEM_BYTES (GROUPS * GSTRIDE)   // 24640 B

__device__ __forceinline__ u64 fma2(u64 a, u64 b, u64 c) {
    u64 d; asm("fma.rn.f32x2 %0, %1, %2, %3;" : "=l"(d) : "l"(a), "l"(b), "l"(c));
    return d;
}
__device__ __forceinline__ u64 mul2(u64 a, u64 b) {
    u64 d; asm("mul.rn.f32x2 %0, %1, %2;" : "=l"(d) : "l"(a), "l"(b));
    return d;
}
__device__ __forceinline__ u64 add2(u64 a, u64 b) {
    u64 d; asm("add.rn.f32x2 %0, %1, %2;" : "=l"(d) : "l"(a), "l"(b));
    return d;
}
__device__ __forceinline__ u64 ex2_2(u64 x) {
    u64 r;
    asm("{\n\t"
        ".reg .f32 lo, hi;\n\t"
        "mov.b64 {lo, hi}, %1;\n\t"
        "ex2.approx.f32 lo, lo;\n\t"
        "ex2.approx.f32 hi, hi;\n\t"
        "mov.b64 %0, {lo, hi};\n\t"
        "}" : "=l"(r) : "l"(x));
    return r;
}
__device__ __forceinline__ u64 pack2(float lo, float hi) {
    u64 r; asm("mov.b64 %0, {%1, %2};" : "=l"(r) : "f"(lo), "f"(hi));
    return r;
}
__device__ __forceinline__ void unpack2(u64 v, float& lo, float& hi) {
    asm("mov.b64 {%0, %1}, %2;" : "=f"(lo), "=f"(hi) : "l"(v));
}
__device__ __forceinline__ float rcpa(float x) {
    float r; asm("rcp.approx.f32 %0, %1;" : "=f"(r) : "f"(x));
    return r;
}
__device__ __forceinline__ u64 lds64(unsigned addr) {
    u64 v; asm("ld.shared.b64 %0, [%1];" : "=l"(v) : "r"(addr));
    return v;
}

__global__ __launch_bounds__(THREADS, 7)
void attn3d_kernel(const float* __restrict__ x,
                   const float* __restrict__ Wq,
                   const float* __restrict__ Wk,
                   const float* __restrict__ Wv,
                   float* __restrict__ out)
{
    extern __shared__ float sm[];
    float* red = sm;   // aliases x region after post-loop barrier (1024 floats)

    const int tid   = threadIdx.x;
    const int cta   = blockIdx.x;
    const int bh    = cta >> 5;
    const int chunk = cta & 31;
    const int b     = bh >> 3;
    const int h     = bh & 7;

    const float* xb = x + (size_t)b * S_LEN * 3;

    // ---- Fill smem: 2-key records [x0 pair][x1 pair][x2 pair], 24B each ----
    #pragma unroll
    for (int i = 0; i < S_LEN / THREADS; ++i) {
        const int k  = tid + i * THREADS;
        const int g  = k >> 9;             // key group (512 keys each)
        const int jc = k & 511;
        const int j  = jc >> 1;            // record in group
        const int c  = jc & 1;             // lane in record
        float* rec = reinterpret_cast<float*>(
            reinterpret_cast<char*>(sm) + g * GSTRIDE + j * 24 + c * 4);
        rec[0] = xb[k * 3 + 0];
        rec[2] = xb[k * 3 + 1];
        rec[4] = xb[k * 3 + 2];
    }

    // ---- 2 queries per thread; fold Wq*Wk*scale; no shift (range-safe) ----
    const int g  = tid >> 5;          // key group == warp id
    const int ql = tid & 31;          // query slot; handles ql and ql+32
    const float* wq = Wq + h * 9;
    const float* wk = Wk + h * 9;
    const float RS = 0.57735026918962576f * 1.4426950408889634f;

    u64 q0p[QPT], q1p[QPT], q2p[QPT];
    #pragma unroll
    for (int qq = 0; qq < QPT; ++qq) {
        const int sq = chunk * QPC + ql + qq * 32;
        const float xq0 = xb[sq * 3 + 0];
        const float xq1 = xb[sq * 3 + 1];
        const float xq2 = xb[sq * 3 + 2];
        const float q0 = xq0 * wq[0] + xq1 * wq[3] + xq2 * wq[6];
        const float q1 = xq0 * wq[1] + xq1 * wq[4] + xq2 * wq[7];
        const float q2 = xq0 * wq[2] + xq1 * wq[5] + xq2 * wq[8];
        const float a0 = RS * (q0 * wk[0] + q1 * wk[1] + q2 * wk[2]);
        const float a1 = RS * (q0 * wk[3] + q1 * wk[4] + q2 * wk[5]);
        const float a2 = RS * (q0 * wk[6] + q1 * wk[7] + q2 * wk[8]);
        q0p[qq] = pack2(a0, a0);
        q1p[qq] = pack2(a1, a1);
        q2p[qq] = pack2(a2, a2);
    }

    __syncthreads();

    unsigned sbase;
    asm("{ .reg .u64 t; cvta.to.shared.u64 t, %1; cvt.u32.u64 %0, t; }"
        : "=r"(sbase) : "l"(sm));
    unsigned p = sbase + g * GSTRIDE;

    // Split l accumulators (per record stream) to break the serial add chain.
    u64 laccA[QPT] = {0ull, 0ull};
    u64 laccB[QPT] = {0ull, 0ull};
    u64 t0[QPT]   = {0ull, 0ull};
    u64 t1[QPT]   = {0ull, 0ull};
    u64 t2[QPT]   = {0ull, 0ull};

    // ---- Inner loop, phase-ordered: loads | all dots | all exps | accums ----
    #pragma unroll 4
    for (int r = 0; r < ITERS; ++r) {
        const u64 A0 = lds64(p);
        const u64 A1 = lds64(p + 8);
        const u64 A2 = lds64(p + 16);
        const u64 B0 = lds64(p + 24);
        const u64 B1 = lds64(p + 32);
        const u64 B2 = lds64(p + 40);
        p += 48;
        // phase 1: all four dot pairs
        const u64 dA0 = fma2(q0p[0], A0, fma2(q1p[0], A1, mul2(q2p[0], A2)));
        const u64 dB0 = fma2(q0p[0], B0, fma2(q1p[0], B1, mul2(q2p[0], B2)));
        const u64 dA1 = fma2(q0p[1], A0, fma2(q1p[1], A1, mul2(q2p[1], A2)));
        const u64 dB1 = fma2(q0p[1], B0, fma2(q1p[1], B1, mul2(q2p[1], B2)));
        // phase 2: all exps
        const u64 pA0 = ex2_2(dA0);
        const u64 pB0 = ex2_2(dB0);
        const u64 pA1 = ex2_2(dA1);
        const u64 pB1 = ex2_2(dB1);
        // phase 3: accumulate
        laccA[0] = add2(laccA[0], pA0);
        laccB[0] = add2(laccB[0], pB0);
        laccA[1] = add2(laccA[1], pA1);
        laccB[1] = add2(laccB[1], pB1);
        t0[0] = fma2(pA0, A0, fma2(pB0, B0, t0[0]));
        t1[0] = fma2(pA0, A1, fma2(pB0, B1, t1[0]));
        t2[0] = fma2(pA0, A2, fma2(pB0, B2, t2[0]));
        t0[1] = fma2(pA1, A0, fma2(pB1, B0, t0[1]));
        t1[1] = fma2(pA1, A1, fma2(pB1, B1, t1[1]));
        t2[1] = fma2(pA1, A2, fma2(pB1, B2, t2[1]));
    }

    // ---- All reads done; alias smem for reduction ----
    __syncthreads();
    #pragma unroll
    for (int qq = 0; qq < QPT; ++qq) {
        const int q = ql + qq * 32;
        float a, c, a2, c2;
        unpack2(laccA[qq], a, c); unpack2(laccB[qq], a2, c2);
        red[0 * 256 + g * 64 + q] = (a + c) + (a2 + c2);
        unpack2(t0[qq], a, c); red[1 * 256 + g * 64 + q] = a + c;
        unpack2(t1[qq], a, c); red[2 * 256 + g * 64 + q] = a + c;
        unpack2(t2[qq], a, c); red[3 * 256 + g * 64 + q] = a + c;
    }
    __syncthreads();

    // ---- 4-way group merge + Wv projection + write both output copies ----
    if (tid < QPC) {
        const float L  = red[0 * 256 + tid] + red[0 * 256 + 64 + tid]
                       + red[0 * 256 + 128 + tid] + red[0 * 256 + 192 + tid];
        const float T0 = red[1 * 256 + tid] + red[1 * 256 + 64 + tid]
                       + red[1 * 256 + 128 + tid] + red[1 * 256 + 192 + tid];
        const float T1 = red[2 * 256 + tid] + red[2 * 256 + 64 + tid]
                       + red[2 * 256 + 128 + tid] + red[2 * 256 + 192 + tid];
        const float T2 = red[3 * 256 + tid] + red[3 * 256 + 64 + tid]
                       + red[3 * 256 + 128 + tid] + red[3 * 256 + 192 + tid];
        const float inv = rcpa(L);
        const float* wv = Wv + h * 9;
        const float r0 = (T0 * wv[0] + T1 * wv[3] + T2 * wv[6]) * inv;
        const float r1 = (T0 * wv[1] + T1 * wv[4] + T2 * wv[7]) * inv;
        const float r2 = (T0 * wv[2] + T1 * wv[5] + T2 * wv[8]) * inv;
        const int base = (bh * S_LEN + chunk * QPC + tid) * 3;
        out[base + 0] = r0;
        out[base + 1] = r1;
        out[base + 2] = r2;
        out[OUT_HALF + base + 0] = r0;
        out[OUT_HALF + base + 1] = r1;
        out[OUT_HALF + base + 2] = r2;
    }
}

extern "C" void kernel_launch(void* const* d_in, const int* in_sizes, int n_in,
                              void* d_out, int out_size)
{
    const float* x  = (const float*)d_in[0];
    const float* Wq = (const float*)d_in[1];
    const float* Wk = (const float*)d_in[2];
    const float* Wv = (const float*)d_in[3];
    float* out = (float*)d_out;

    cudaFuncSetAttribute(attn3d_kernel,
                         cudaFuncAttributeMaxDynamicSharedMemorySize, SMEM_BYTES);
    attn3d_kernel<<<N_CTA, THREADS, SMEM_BYTES>>>(x, Wq, Wk, Wv, out);
}

// round 15
// speedup vs baseline: 1.0752x; 1.0103x over previous
#include <cuda_runtime.h>

typedef unsigned long long u64;
typedef unsigned int u32;

// B=4, H=8, S=2048, D=3 (fixed by reference)
#define S_LEN   2048
#define QPC     64            // queries per CTA: 4 warps x 16 (M=16 per warp)
#define THREADS 128
#define N_CTA   1024          // 32 bh * 32 chunks
#define CHUNKS  256           // 8-key chunks
#define OUT_HALF (32 * S_LEN * 3)

// smem: 256 chunks * 96B (3 comps * 4 pairs * 8B, pair = key c | key c+4)
//       + 8B ones + 8B zeros
#define SM_ONES  24576
#define SM_ZEROS 24584
#define SMEM_BYTES 24592

__device__ __forceinline__ u64 fma2(u64 a, u64 b, u64 c) {
    u64 d; asm("fma.rn.f32x2 %0, %1, %2, %3;" : "=l"(d) : "l"(a), "l"(b), "l"(c));
    return d;
}
__device__ __forceinline__ u64 mul2(u64 a, u64 b) {
    u64 d; asm("mul.rn.f32x2 %0, %1, %2;" : "=l"(d) : "l"(a), "l"(b));
    return d;
}
__device__ __forceinline__ u64 ex2_2(u64 x) {
    u64 r;
    asm("{\n\t.reg .f32 lo, hi;\n\tmov.b64 {lo, hi}, %1;\n\t"
        "ex2.approx.f32 lo, lo;\n\tex2.approx.f32 hi, hi;\n\t"
        "mov.b64 %0, {lo, hi};\n\t}" : "=l"(r) : "l"(x));
    return r;
}
__device__ __forceinline__ u64 pack2(float lo, float hi) {
    u64 r; asm("mov.b64 %0, {%1, %2};" : "=l"(r) : "f"(lo), "f"(hi));
    return r;
}
__device__ __forceinline__ void unpack2u(u64 v, u32& lo, u32& hi) {
    asm("mov.b64 {%0, %1}, %2;" : "=r"(lo), "=r"(hi) : "l"(v));
}
__device__ __forceinline__ float rcpa(float x) {
    float r; asm("rcp.approx.f32 %0, %1;" : "=f"(r) : "f"(x));
    return r;
}
__device__ __forceinline__ u64 lds64(u32 addr) {
    u64 v; asm("ld.shared.b64 %0, [%1];" : "=l"(v) : "r"(addr));
    return v;
}
__device__ __forceinline__ u32 f2tf32(float f) {
    u32 r; asm("cvt.rna.tf32.f32 %0, %1;" : "=r"(r) : "f"(f));
    return r;
}
// m16n8k8 tf32 HMMA (base PTX ISA, sm_80+; runs on Blackwell fallback HMMA)
__device__ __forceinline__ void mma1688(float& d0, float& d1, float& d2, float& d3,
                                        u32 a0, u32 a1, u32 a2, u32 a3,
                                        u32 b0, u32 b1)
{
    asm volatile(
        "mma.sync.aligned.m16n8k8.row.col.f32.tf32.tf32.f32 "
        "{%0,%1,%2,%3}, {%4,%5,%6,%7}, {%8,%9}, {%0,%1,%2,%3};"
        : "+f"(d0), "+f"(d1), "+f"(d2), "+f"(d3)
        : "r"(a0), "r"(a1), "r"(a2), "r"(a3), "r"(b0), "r"(b1));
}

__global__ __launch_bounds__(THREADS, 7)
void attn3d_mma_kernel(const float* __restrict__ x,
                       const float* __restrict__ Wq,
                       const float* __restrict__ Wk,
                       const float* __restrict__ Wv,
                       float* __restrict__ out)
{
    extern __shared__ char smc[];

    const int tid   = threadIdx.x;
    const int cta   = blockIdx.x;
    const int bh    = cta >> 5;
    const int chunk = cta & 31;
    const int b     = bh >> 3;
    const int h     = bh & 7;
    const int w     = tid >> 5;       // warp: queries w*16 .. w*16+15
    const int lane  = tid & 31;
    const int g     = lane >> 2;      // A row group / B col (n)
    const int c     = lane & 3;       // A col / B row (key pair index)

    u32 sbase;
    asm("{ .reg .u64 t; cvta.to.shared.u64 t, %1; cvt.u32.u64 %0, t; }"
        : "=r"(sbase) : "l"(smc));

    const float* xb = x + (size_t)b * S_LEN * 3;

    // ---- Fill smem: per chunk (8 keys) 3 comps x 4 pairs; values tf32-truncated ----
    #pragma unroll
    for (int i = 0; i < S_LEN / THREADS; ++i) {
        const int k  = tid + i * THREADS;
        const int ch = k >> 3;
        const int ki = k & 7;
        const int pc = ki & 3;            // pair index
        const int hf = ki >> 2;           // 0: key c (lo), 1: key c+4 (hi)
        u32* base = reinterpret_cast<u32*>(smc + ch * 96 + pc * 8 + hf * 4);
        base[0]  = f2tf32(xb[k * 3 + 0]);     // comp0 at +0
        base[8]  = f2tf32(xb[k * 3 + 1]);     // comp1 at +32B
        base[16] = f2tf32(xb[k * 3 + 2]);     // comp2 at +64B
    }
    if (tid == 0) {
        *reinterpret_cast<float2*>(smc + SM_ONES)  = make_float2(1.0f, 1.0f);
        *reinterpret_cast<float2*>(smc + SM_ZEROS) = make_float2(0.0f, 0.0f);
    }

    // ---- Query constants for rows g and g+8 of this warp's 16 queries ----
    const float* wq = Wq + h * 9;
    const float* wk = Wk + h * 9;
    const float RS = 0.57735026918962576f * 1.4426950408889634f;
    u64 q0p[2], q1p[2], q2p[2];
    #pragma unroll
    for (int qq = 0; qq < 2; ++qq) {
        const int sq = chunk * QPC + w * 16 + g + qq * 8;
        const float xq0 = xb[sq * 3 + 0];
        const float xq1 = xb[sq * 3 + 1];
        const float xq2 = xb[sq * 3 + 2];
        const float q0 = xq0 * wq[0] + xq1 * wq[3] + xq2 * wq[6];
        const float q1 = xq0 * wq[1] + xq1 * wq[4] + xq2 * wq[7];
        const float q2 = xq0 * wq[2] + xq1 * wq[5] + xq2 * wq[8];
        const float a0 = RS * (q0 * wk[0] + q1 * wk[1] + q2 * wk[2]);
        const float a1 = RS * (q0 * wk[3] + q1 * wk[4] + q2 * wk[5]);
        const float a2 = RS * (q0 * wk[6] + q1 * wk[7] + q2 * wk[8]);
        q0p[qq] = pack2(a0, a0);
        q1p[qq] = pack2(a1, a1);
        q2p[qq] = pack2(a2, a2);
    }

    __syncthreads();

    // ---- per-thread pointers ----
    u32 p = sbase + (u32)c * 8u;               // dot loads: comps at +0,+32,+64
    u32 bp;                                     // B-fragment pair pointer
    u32 bstride;
    if (g < 3)       { bp = sbase + (u32)g * 32u + (u32)c * 8u; bstride = 96; }
    else if (g == 3) { bp = sbase + SM_ONES;  bstride = 0; }
    else             { bp = sbase + SM_ZEROS; bstride = 0; }

    float d0 = 0.f, d1 = 0.f, d2 = 0.f, d3 = 0.f;

    // ---- Main loop: 256 chunks of 8 keys ----
    #pragma unroll 4
    for (int r = 0; r < CHUNKS; ++r) {
        const u64 X0 = lds64(p);
        const u64 X1 = lds64(p + 32);
        const u64 X2 = lds64(p + 64);
        p += 96;
        const u64 bpair = lds64(bp);
        bp += bstride;

        const u64 dA = fma2(q0p[0], X0, fma2(q1p[0], X1, mul2(q2p[0], X2)));
        const u64 dB = fma2(q0p[1], X0, fma2(q1p[1], X1, mul2(q2p[1], X2)));
        const u64 eA = ex2_2(dA);       // p for (row g,   keys c | c+4)
        const u64 eB = ex2_2(dB);       // p for (row g+8, keys c | c+4)

        u32 a0, a2, a1, a3, b0, b1;
        unpack2u(eA, a0, a2);
        unpack2u(eB, a1, a3);
        unpack2u(bpair, b0, b1);
        a0 = f2tf32(__uint_as_float(a0));
        a1 = f2tf32(__uint_as_float(a1));
        a2 = f2tf32(__uint_as_float(a2));
        a3 = f2tf32(__uint_as_float(a3));

        mma1688(d0, d1, d2, d3, a0, a1, a2, a3, b0, b1);
    }

    // ---- Epilogue: thread (g,c) holds D[g][2c],D[g][2c+1],D[g+8][2c],D[g+8][2c+1]
    // row r needs cols 0..3 = (c=0: t0,t1) + (c=1: t2,l)
    const float s0 = __shfl_down_sync(0xffffffffu, d0, 1);   // t2 (row g)
    const float s1 = __shfl_down_sync(0xffffffffu, d1, 1);   // l  (row g)
    const float s2 = __shfl_down_sync(0xffffffffu, d2, 1);   // t2 (row g+8)
    const float s3 = __shfl_down_sync(0xffffffffu, d3, 1);   // l  (row g+8)

    if (c == 0) {
        const float* wv = Wv + h * 9;
        #pragma unroll
        for (int qq = 0; qq < 2; ++qq) {
            const float T0 = qq ? d2 : d0;
            const float T1 = qq ? d3 : d1;
            const float T2 = qq ? s2 : s0;
            const float L  = qq ? s3 : s1;
            const float inv = rcpa(L);
            const float r0 = (T0 * wv[0] + T1 * wv[3] + T2 * wv[6]) * inv;
            const float r1 = (T0 * wv[1] + T1 * wv[4] + T2 * wv[7]) * inv;
            const float r2 = (T0 * wv[2] + T1 * wv[5] + T2 * wv[8]) * inv;
            const int sq = chunk * QPC + w * 16 + g + qq * 8;
            const int base = (bh * S_LEN + sq) * 3;
            out[base + 0] = r0;
            out[base + 1] = r1;
            out[base + 2] = r2;
            out[OUT_HALF + base + 0] = r0;
            out[OUT_HALF + base + 1] = r1;
            out[OUT_HALF + base + 2] = r2;
        }
    }
}

extern "C" void kernel_launch(void* const* d_in, const int* in_sizes, int n_in,
                              void* d_out, int out_size)
{
    const float* x  = (const float*)d_in[0];
    const float* Wq = (const float*)d_in[1];
    const float* Wk = (const float*)d_in[2];
    const float* Wv = (const float*)d_in[3];
    float* out = (float*)d_out;

    cudaFuncSetAttribute(attn3d_mma_kernel,
                         cudaFuncAttributeMaxDynamicSharedMemorySize, SMEM_BYTES);
    attn3d_mma_kernel<<<N_CTA, THREADS, SMEM_BYTES>>>(x, Wq, Wk, Wv, out);
}

// round 17
// speedup vs baseline: 1.2645x; 1.1761x over previous
#include <cuda_runtime.h>

typedef unsigned long long u64;
typedef unsigned int u32;

// B=4, H=8, S=2048, D=3 (fixed by reference)
#define S_LEN   2048
#define QPC     64            // queries per CTA: 4 warps x 16 (M=16 per warp)
#define THREADS 128
#define N_CTA   1024          // 32 bh * 32 chunks
#define CHUNKS  256           // 8-key chunks
#define OUT_HALF (32 * S_LEN * 3)

// smem: 256 chunks * 96B (3 comps * 4 pairs * 8B, pair = key c | key c+4)
//       + 8B ones + 8B zeros
#define SM_ONES  24576
#define SM_ZEROS 24584
#define SMEM_BYTES 24592

__device__ __forceinline__ u64 fma2(u64 a, u64 b, u64 c) {
    u64 d; asm("fma.rn.f32x2 %0, %1, %2, %3;" : "=l"(d) : "l"(a), "l"(b), "l"(c));
    return d;
}
__device__ __forceinline__ u64 mul2(u64 a, u64 b) {
    u64 d; asm("mul.rn.f32x2 %0, %1, %2;" : "=l"(d) : "l"(a), "l"(b));
    return d;
}
__device__ __forceinline__ u64 ex2_2(u64 x) {
    u64 r;
    asm("{\n\t.reg .f32 lo, hi;\n\tmov.b64 {lo, hi}, %1;\n\t"
        "ex2.approx.f32 lo, lo;\n\tex2.approx.f32 hi, hi;\n\t"
        "mov.b64 %0, {lo, hi};\n\t}" : "=l"(r) : "l"(x));
    return r;
}
__device__ __forceinline__ u64 pack2(float lo, float hi) {
    u64 r; asm("mov.b64 %0, {%1, %2};" : "=l"(r) : "f"(lo), "f"(hi));
    return r;
}
__device__ __forceinline__ void unpack2u(u64 v, u32& lo, u32& hi) {
    asm("mov.b64 {%0, %1}, %2;" : "=r"(lo), "=r"(hi) : "l"(v));
}
__device__ __forceinline__ float rcpa(float x) {
    float r; asm("rcp.approx.f32 %0, %1;" : "=f"(r) : "f"(x));
    return r;
}
__device__ __forceinline__ u64 lds64(u32 addr) {
    u64 v; asm("ld.shared.b64 %0, [%1];" : "=l"(v) : "r"(addr));
    return v;
}
// m16n8k8 tf32 HMMA (base PTX ISA, sm_80+). Operands are raw f32 bits:
// the tf32 datapath ignores the low 13 mantissa bits (truncation) — the
// cutlass fast-f32 convention. Saves 4 cvt.rna.tf32 per inner iteration.
__device__ __forceinline__ void mma1688(float& d0, float& d1, float& d2, float& d3,
                                        u32 a0, u32 a1, u32 a2, u32 a3,
                                        u32 b0, u32 b1)
{
    asm volatile(
        "mma.sync.aligned.m16n8k8.row.col.f32.tf32.tf32.f32 "
        "{%0,%1,%2,%3}, {%4,%5,%6,%7}, {%8,%9}, {%0,%1,%2,%3};"
        : "+f"(d0), "+f"(d1), "+f"(d2), "+f"(d3)
        : "r"(a0), "r"(a1), "r"(a2), "r"(a3), "r"(b0), "r"(b1));
}

__global__ __launch_bounds__(THREADS, 7)
void attn3d_mma_kernel(const float* __restrict__ x,
                       const float* __restrict__ Wq,
                       const float* __restrict__ Wk,
                       const float* __restrict__ Wv,
                       float* __restrict__ out)
{
    extern __shared__ char smc[];

    const int tid   = threadIdx.x;
    const int cta   = blockIdx.x;
    const int bh    = cta >> 5;
    const int chunk = cta & 31;
    const int b     = bh >> 3;
    const int h     = bh & 7;
    const int w     = tid >> 5;       // warp: queries w*16 .. w*16+15
    const int lane  = tid & 31;
    const int g     = lane >> 2;      // A row group / B col (n)
    const int c     = lane & 3;       // A col / B row (key pair index)

    u32 sbase;
    asm("{ .reg .u64 t; cvta.to.shared.u64 t, %1; cvt.u32.u64 %0, t; }"
        : "=r"(sbase) : "l"(smc));

    const float* xb = x + (size_t)b * S_LEN * 3;

    // ---- Fill smem: per chunk (8 keys) 3 comps x 4 pairs, RAW f32 bits ----
    #pragma unroll
    for (int i = 0; i < S_LEN / THREADS; ++i) {
        const int k  = tid + i * THREADS;
        const int ch = k >> 3;
        const int ki = k & 7;
        const int pc = ki & 3;            // pair index
        const int hf = ki >> 2;           // 0: key c (lo), 1: key c+4 (hi)
        float* base = reinterpret_cast<float*>(smc + ch * 96 + pc * 8 + hf * 4);
        base[0]  = xb[k * 3 + 0];     // comp0 at +0
        base[8]  = xb[k * 3 + 1];     // comp1 at +32B
        base[16] = xb[k * 3 + 2];     // comp2 at +64B
    }
    if (tid == 0) {
        *reinterpret_cast<float2*>(smc + SM_ONES)  = make_float2(1.0f, 1.0f);
        *reinterpret_cast<float2*>(smc + SM_ZEROS) = make_float2(0.0f, 0.0f);
    }

    // ---- Query constants for rows g and g+8 of this warp's 16 queries ----
    const float* wq = Wq + h * 9;
    const float* wk = Wk + h * 9;
    const float RS = 0.57735026918962576f * 1.4426950408889634f;
    u64 q0p[2], q1p[2], q2p[2];
    #pragma unroll
    for (int qq = 0; qq < 2; ++qq) {
        const int sq = chunk * QPC + w * 16 + g + qq * 8;
        const float xq0 = xb[sq * 3 + 0];
        const float xq1 = xb[sq * 3 + 1];
        const float xq2 = xb[sq * 3 + 2];
        const float q0 = xq0 * wq[0] + xq1 * wq[3] + xq2 * wq[6];
        const float q1 = xq0 * wq[1] + xq1 * wq[4] + xq2 * wq[7];
        const float q2 = xq0 * wq[2] + xq1 * wq[5] + xq2 * wq[8];
        const float a0 = RS * (q0 * wk[0] + q1 * wk[1] + q2 * wk[2]);
        const float a1 = RS * (q0 * wk[3] + q1 * wk[4] + q2 * wk[5]);
        const float a2 = RS * (q0 * wk[6] + q1 * wk[7] + q2 * wk[8]);
        q0p[qq] = pack2(a0, a0);
        q1p[qq] = pack2(a1, a1);
        q2p[qq] = pack2(a2, a2);
    }

    __syncthreads();

    // ---- per-thread pointers ----
    u32 p = sbase + (u32)c * 8u;               // dot loads: comps at +0,+32,+64
    u32 bp;                                     // B-fragment pair pointer
    u32 bstride;
    if (g < 3)       { bp = sbase + (u32)g * 32u + (u32)c * 8u; bstride = 96; }
    else if (g == 3) { bp = sbase + SM_ONES;  bstride = 0; }
    else             { bp = sbase + SM_ZEROS; bstride = 0; }

    float d0 = 0.f, d1 = 0.f, d2 = 0.f, d3 = 0.f;

    // ---- Main loop: 256 chunks of 8 keys ----
    #pragma unroll 8
    for (int r = 0; r < CHUNKS; ++r) {
        const u64 X0 = lds64(p);
        const u64 X1 = lds64(p + 32);
        const u64 X2 = lds64(p + 64);
        p += 96;
        const u64 bpair = lds64(bp);
        bp += bstride;

        const u64 dA = fma2(q0p[0], X0, fma2(q1p[0], X1, mul2(q2p[0], X2)));
        const u64 dB = fma2(q0p[1], X0, fma2(q1p[1], X1, mul2(q2p[1], X2)));
        const u64 eA = ex2_2(dA);       // p for (row g,   keys c | c+4)
        const u64 eB = ex2_2(dB);       // p for (row g+8, keys c | c+4)

        u32 a0, a2, a1, a3, b0, b1;
        unpack2u(eA, a0, a2);
        unpack2u(eB, a1, a3);
        unpack2u(bpair, b0, b1);

        mma1688(d0, d1, d2, d3, a0, a1, a2, a3, b0, b1);
    }

    // ---- Epilogue: thread (g,c) holds D[g][2c],D[g][2c+1],D[g+8][2c],D[g+8][2c+1]
    // row r needs cols 0..3 = (c=0: t0,t1) + (c=1: t2,l)
    const float s0 = __shfl_down_sync(0xffffffffu, d0, 1);   // t2 (row g)
    const float s1 = __shfl_down_sync(0xffffffffu, d1, 1);   // l  (row g)
    const float s2 = __shfl_down_sync(0xffffffffu, d2, 1);   // t2 (row g+8)
    const float s3 = __shfl_down_sync(0xffffffffu, d3, 1);   // l  (row g+8)

    if (c == 0) {
        const float* wv = Wv + h * 9;
        #pragma unroll
        for (int qq = 0; qq < 2; ++qq) {
            const float T0 = qq ? d2 : d0;
            const float T1 = qq ? d3 : d1;
            const float T2 = qq ? s2 : s0;
            const float L  = qq ? s3 : s1;
            const float inv = rcpa(L);
            const float r0 = (T0 * wv[0] + T1 * wv[3] + T2 * wv[6]) * inv;
            const float r1 = (T0 * wv[1] + T1 * wv[4] + T2 * wv[7]) * inv;
            const float r2 = (T0 * wv[2] + T1 * wv[5] + T2 * wv[8]) * inv;
            const int sq = chunk * QPC + w * 16 + g + qq * 8;
            const int base = (bh * S_LEN + sq) * 3;
            out[base + 0] = r0;
            out[base + 1] = r1;
            out[base + 2] = r2;
            out[OUT_HALF + base + 0] = r0;
            out[OUT_HALF + base + 1] = r1;
            out[OUT_HALF + base + 2] = r2;
        }
    }
}

extern "C" void kernel_launch(void* const* d_in, const int* in_sizes, int n_in,
                              void* d_out, int out_size)
{
    const float* x  = (const float*)d_in[0];
    const float* Wq = (const float*)d_in[1];
    const float* Wk = (const float*)d_in[2];
    const float* Wv = (const float*)d_in[3];
    float* out = (float*)d_out;

    cudaFuncSetAttribute(attn3d_mma_kernel,
                         cudaFuncAttributeMaxDynamicSharedMemorySize, SMEM_BYTES);
    attn3d_mma_kernel<<<N_CTA, THREADS, SMEM_BYTES>>>(x, Wq, Wk, Wv, out);
}